// round 7
// baseline (speedup 1.0000x reference)
#include <cuda_runtime.h>
#include <cuda_bf16.h>
#include <cstdint>

#define SEQ 2048
#define NB 2
#define NH 16
#define AD 64
#define DM 1024
#define BH (NB*NH)
#define NPE 33
typedef __nv_bfloat16 bf16;

// ---------------- scratch (no allocation allowed) ----------------
__device__ bf16 g_Wth[(size_t)4*DM*DM], g_Wtl[(size_t)4*DM*DM];
__device__ bf16 g_Ih[(size_t)NB*SEQ*DM],  g_Il[(size_t)NB*SEQ*DM];
__device__ bf16 g_Qh[(size_t)BH*SEQ*AD],  g_Ql[(size_t)BH*SEQ*AD];
__device__ bf16 g_Kh[(size_t)BH*SEQ*AD],  g_Kl[(size_t)BH*SEQ*AD];
__device__ bf16 g_Vh[(size_t)BH*SEQ*AD],  g_Vl[(size_t)BH*SEQ*AD];
__device__ bf16 g_Ch[(size_t)NB*SEQ*DM],  g_Cl[(size_t)NB*SEQ*DM];
__device__ float g_P[(size_t)BH*SEQ*NPE];

// ---------------- helpers ----------------
__device__ __forceinline__ uint32_t s2u(const void* p) {
    uint32_t a;
    asm("{ .reg .u64 t; cvta.to.shared.u64 t, %1; cvt.u32.u64 %0, t; }" : "=r"(a) : "l"(p));
    return a;
}
__device__ __forceinline__ uint32_t swz(uint32_t o) { return o ^ ((o >> 3) & 0x70); }

__device__ __forceinline__ void ldsm4(uint32_t* r, uint32_t a) {
    asm volatile("ldmatrix.sync.aligned.m8n8.x4.shared.b16 {%0,%1,%2,%3}, [%4];"
                 : "=r"(r[0]), "=r"(r[1]), "=r"(r[2]), "=r"(r[3]) : "r"(a));
}
__device__ __forceinline__ void ldsm4t(uint32_t* r, uint32_t a) {
    asm volatile("ldmatrix.sync.aligned.m8n8.x4.trans.shared.b16 {%0,%1,%2,%3}, [%4];"
                 : "=r"(r[0]), "=r"(r[1]), "=r"(r[2]), "=r"(r[3]) : "r"(a));
}
__device__ __forceinline__ void mma_bf16(float* d, const uint32_t* a, const uint32_t* b) {
    asm volatile("mma.sync.aligned.m16n8k16.row.col.f32.bf16.bf16.f32 "
                 "{%0,%1,%2,%3}, {%4,%5,%6,%7}, {%8,%9}, {%0,%1,%2,%3};"
                 : "+f"(d[0]), "+f"(d[1]), "+f"(d[2]), "+f"(d[3])
                 : "r"(a[0]), "r"(a[1]), "r"(a[2]), "r"(a[3]), "r"(b[0]), "r"(b[1]));
}
#define CP16(dst, src) \
    asm volatile("cp.async.cg.shared.global [%0], [%1], 16;" :: "r"(dst), "l"(src))
#define CPCOMMIT asm volatile("cp.async.commit_group;" ::: "memory")
#define CPWAIT(n) asm volatile("cp.async.wait_group %0;" :: "n"(n) : "memory")

__device__ __forceinline__ void packhl(float x0, float x1, uint32_t& ph, uint32_t& pl) {
    bf16 h0 = __float2bfloat16(x0), h1 = __float2bfloat16(x1);
    ph = ((uint32_t)__bfloat16_as_ushort(h1) << 16) | __bfloat16_as_ushort(h0);
    float l0 = x0 - __bfloat162float(h0), l1 = x1 - __bfloat162float(h1);
    asm("cvt.rn.bf16x2.f32 %0, %1, %2;" : "=r"(pl) : "f"(l1), "f"(l0));
}
__device__ __forceinline__ void cvt_hl(float4 v, uint2& h2, uint2& l2) {
    uint32_t a, b, c, d;
    packhl(v.x, v.y, a, c);
    packhl(v.z, v.w, b, d);
    h2 = make_uint2(a, b); l2 = make_uint2(c, d);
}

// ---------------- prep kernels ----------------
__global__ __launch_bounds__(256)
void split_in(const float4* __restrict__ x, bf16* __restrict__ h, bf16* __restrict__ l)
{
    size_t i = (size_t)blockIdx.x * 256 + threadIdx.x;
    float4 v = x[i];
    uint2 h2, l2; cvt_hl(v, h2, l2);
    *reinterpret_cast<uint2*>(h + i * 4) = h2;
    *reinterpret_cast<uint2*>(l + i * 4) = l2;
}

__global__ __launch_bounds__(256)
void transp_w(const float* __restrict__ W0, const float* __restrict__ W1,
              const float* __restrict__ W2, const float* __restrict__ W3,
              bf16* __restrict__ oh, bf16* __restrict__ ol)
{
    __shared__ float t[32][33];
    const float* W = (blockIdx.z == 0) ? W0 : (blockIdx.z == 1) ? W1
                   : (blockIdx.z == 2) ? W2 : W3;
    bf16* Oh = oh + (size_t)blockIdx.z * DM * DM;
    bf16* Ol = ol + (size_t)blockIdx.z * DM * DM;
    const int tx = threadIdx.x & 31, ty = threadIdx.x >> 5;
    const int x = blockIdx.x * 32 + tx, y = blockIdx.y * 32 + ty;
    #pragma unroll
    for (int j = 0; j < 32; j += 8) t[ty + j][tx] = W[(size_t)(y + j) * DM + x];
    __syncthreads();
    const int xo = blockIdx.y * 32 + tx, yo = blockIdx.x * 32 + ty;
    #pragma unroll
    for (int j = 0; j < 32; j += 8) {
        float v = t[tx][ty + j];
        bf16 h = __float2bfloat16(v);
        Oh[(size_t)(yo + j) * DM + xo] = h;
        Ol[(size_t)(yo + j) * DM + xo] = __float2bfloat16(v - __bfloat162float(h));
    }
}

// ---------------------------------------------------------------------------
// split-bf16 GEMM, pre-split operands.  C[128,128] = A[128,K] * B[128,K]^T.
// EPI 0: fp32 [m][DM].   EPI 1: hi/lo bf16 head-major [bh][s][d].
// ---------------------------------------------------------------------------
template<int EPI>
__global__ __launch_bounds__(256, 1)
void gemm_hl(const bf16* __restrict__ Ah_g, const bf16* __restrict__ Al_g,
             const bf16* __restrict__ Bh_g, const bf16* __restrict__ Bl_g,
             float* __restrict__ Cf, bf16* __restrict__ Oh, bf16* __restrict__ Ol,
             int K)
{
    extern __shared__ char dsm[];
    const uint32_t raw = s2u(dsm);
    const uint32_t sb  = (raw + 1023u) & ~1023u;
    const int tid = threadIdx.x, wid = tid >> 5, lane = tid & 31;
    const int bm = blockIdx.y * 128, bn = blockIdx.x * 128;
    const int wm = (wid >> 1) * 32, wn = (wid & 1) * 64;

    float acc[2][8][4] = {};

    auto load_stage = [&](int buf, int k0) {
        uint32_t base = sb + (uint32_t)buf * 65536u;
        #pragma unroll
        for (int i = 0; i < 16; i++) {
            int c = tid + i * 256;
            int t_ = c >> 10, row = (c >> 3) & 127, j = c & 7;
            const bf16* src =
                (t_ == 0) ? Ah_g + (size_t)(bm + row) * K + k0 + j * 8 :
                (t_ == 1) ? Al_g + (size_t)(bm + row) * K + k0 + j * 8 :
                (t_ == 2) ? Bh_g + (size_t)(bn + row) * K + k0 + j * 8 :
                            Bl_g + (size_t)(bn + row) * K + k0 + j * 8;
            uint32_t dst = base + (uint32_t)t_ * 16384u +
                           swz((uint32_t)row * 128u + (uint32_t)j * 16u);
            CP16(dst, src);
        }
        CPCOMMIT;
    };

    const int NS = K / 64;
    load_stage(0, 0);
    for (int s = 0; s < NS; s++) {
        if (s + 1 < NS) { load_stage((s + 1) & 1, (s + 1) * 64); CPWAIT(1); }
        else           { CPWAIT(0); }
        __syncthreads();
        const uint32_t base = sb + (uint32_t)(s & 1) * 65536u;
        const uint32_t AhB = base, AlB = base + 16384u, BhB = base + 32768u, BlB = base + 49152u;
        #pragma unroll
        for (int kk = 0; kk < 4; kk++) {
            const uint32_t kB = (uint32_t)kk * 32u;
            uint32_t ah[2][4], al_[2][4];
            const uint32_t aoff = (((uint32_t)lane >> 4) << 4) + kB;
            #pragma unroll
            for (int mt = 0; mt < 2; mt++) {
                const uint32_t sw = swz((uint32_t)(wm + mt * 16 + (lane & 15)) * 128u + aoff);
                ldsm4(ah[mt], AhB + sw);
                ldsm4(al_[mt], AlB + sw);
            }
            const uint32_t boff = ((((uint32_t)lane >> 3) & 1u) << 4) + kB;
            const uint32_t brow = (uint32_t)(wn + (lane & 7) + ((lane >> 4) << 3));
            #pragma unroll
            for (int g = 0; g < 4; g++) {
                uint32_t bh4[4], bl4[4];
                const uint32_t sw = swz((brow + (uint32_t)g * 16u) * 128u + boff);
                ldsm4(bh4, BhB + sw);
                ldsm4(bl4, BlB + sw);
                #pragma unroll
                for (int mt = 0; mt < 2; mt++)
                    #pragma unroll
                    for (int q = 0; q < 2; q++) {
                        mma_bf16(acc[mt][g * 2 + q], ah[mt],  bh4 + q * 2);
                        mma_bf16(acc[mt][g * 2 + q], ah[mt],  bl4 + q * 2);
                        mma_bf16(acc[mt][g * 2 + q], al_[mt], bh4 + q * 2);
                    }
            }
        }
        __syncthreads();
    }

    #pragma unroll
    for (int mt = 0; mt < 2; mt++)
        #pragma unroll
        for (int nt = 0; nt < 8; nt++) {
            const int m = bm + wm + mt * 16 + (lane >> 2);
            const int n = bn + wn + nt * 8 + (lane & 3) * 2;
            #pragma unroll
            for (int rr = 0; rr < 2; rr++) {
                const int mm = m + rr * 8;
                const float x0 = acc[mt][nt][rr * 2 + 0], x1 = acc[mt][nt][rr * 2 + 1];
                if constexpr (EPI == 0) {
                    *reinterpret_cast<float2*>(Cf + (size_t)mm * DM + n) = make_float2(x0, x1);
                } else {
                    const int b_ = mm >> 11, s_ = mm & 2047, h_ = n >> 6, d_ = n & 63;
                    const size_t o = (((size_t)(b_ * NH + h_)) * SEQ + s_) * AD + d_;
                    uint32_t ph, pl; packhl(x0, x1, ph, pl);
                    *reinterpret_cast<uint32_t*>(Oh + o) = ph;
                    *reinterpret_cast<uint32_t*>(Ol + o) = pl;
                }
            }
        }
}

// ---------------------------------------------------------------------------
// fused flash attention: (QK^T + bias)/8 -> online softmax -> @V
// grid (SEQ/128, BH), 256 threads, warp owns 16 q-rows.
// ---------------------------------------------------------------------------
__global__ __launch_bounds__(256, 1)
void flash_attn(const bf16* __restrict__ Qh_g, const bf16* __restrict__ Ql_g,
                const bf16* __restrict__ Kh_g, const bf16* __restrict__ Kl_g,
                const bf16* __restrict__ Vh_g, const bf16* __restrict__ Vl_g,
                const float* __restrict__ Pr,
                bf16* __restrict__ Ch, bf16* __restrict__ Cl)
{
    extern __shared__ char dsm[];
    const uint32_t raw = s2u(dsm);
    const uint32_t sb  = (raw + 1023u) & ~1023u;
    char* sp = dsm + (sb - raw);
    const int tid = threadIdx.x, wid = tid >> 5, lane = tid & 31;
    const int bh = blockIdx.y, bm = blockIdx.x * 128;
    const int wm = wid * 16;

    const bf16* Qh = Qh_g + ((size_t)bh * SEQ + bm) * AD;
    const bf16* Ql = Ql_g + ((size_t)bh * SEQ + bm) * AD;
    const bf16* Kh = Kh_g + (size_t)bh * SEQ * AD;
    const bf16* Kl = Kl_g + (size_t)bh * SEQ * AD;
    const bf16* Vh = Vh_g + (size_t)bh * SEQ * AD;
    const bf16* Vl = Vl_g + (size_t)bh * SEQ * AD;

    constexpr uint32_t QOFF = 0, STG = 32768, PROW = 32768 + 2 * 65536;
    float* prow = reinterpret_cast<float*>(sp + PROW);

    auto load_stage = [&](int buf, int s0) {
        uint32_t base = sb + STG + (uint32_t)buf * 65536u;
        #pragma unroll
        for (int i = 0; i < 16; i++) {
            int c = tid + i * 256;
            int t_ = c >> 10, row = (c >> 3) & 127, j = c & 7;
            const bf16* src =
                (t_ == 0) ? Kh + (size_t)(s0 + row) * AD + j * 8 :
                (t_ == 1) ? Kl + (size_t)(s0 + row) * AD + j * 8 :
                (t_ == 2) ? Vh + (size_t)(s0 + row) * AD + j * 8 :
                            Vl + (size_t)(s0 + row) * AD + j * 8;
            uint32_t dst = base + (uint32_t)t_ * 16384u +
                           swz((uint32_t)row * 128u + (uint32_t)j * 16u);
            CP16(dst, src);
        }
        CPCOMMIT;
    };

    // Q tiles (hi/lo) + stage0 in first group
    {
        #pragma unroll
        for (int i = 0; i < 8; i++) {
            int c = tid + i * 256;
            int t_ = c >> 10, row = (c >> 3) & 127, j = c & 7;
            const bf16* src = (t_ ? Ql : Qh) + (size_t)row * AD + j * 8;
            uint32_t dst = sb + QOFF + (uint32_t)t_ * 16384u +
                           swz((uint32_t)row * 128u + (uint32_t)j * 16u);
            CP16(dst, src);
        }
    }
    load_stage(0, 0);   // commits Q + stage0 together

    for (int i = tid; i < 128 * NPE; i += 256)
        prow[i] = Pr[((size_t)bh * SEQ + bm) * NPE + i];

    float ctx[8][4] = {};
    float mrun0 = -1e30f, mrun1 = -1e30f, lrun0 = 0.f, lrun1 = 0.f;
    uint32_t qah[4][4], qal[4][4];
    float blo0 = 0.f, blo1 = 0.f, bhi0 = 0.f, bhi1 = 0.f;
    const int rl0 = wm + (lane >> 2), rl1 = rl0 + 8;

    for (int st = 0; st < 16; st++) {
        if (st + 1 < 16) { load_stage((st + 1) & 1, (st + 1) * 128); CPWAIT(1); }
        else             { CPWAIT(0); }
        __syncthreads();

        if (st == 0) {
            #pragma unroll
            for (int kk = 0; kk < 4; kk++) {
                const uint32_t aoff = (((uint32_t)lane >> 4) << 4) + (uint32_t)kk * 32u;
                const uint32_t sw = swz((uint32_t)(wm + (lane & 15)) * 128u + aoff);
                ldsm4(qah[kk], sb + QOFF + sw);
                ldsm4(qal[kk], sb + QOFF + 16384u + sw);
            }
            blo0 = prow[rl0 * NPE + 0];  bhi0 = prow[rl0 * NPE + 32];
            blo1 = prow[rl1 * NPE + 0];  bhi1 = prow[rl1 * NPE + 32];
        }

        const uint32_t base = sb + STG + (uint32_t)(st & 1) * 65536u;
        const uint32_t KhB = base, KlB = base + 16384u, VhB = base + 32768u, VlB = base + 49152u;

        // ---- S = Q K^T ----
        float tS[16][4];
        #pragma unroll
        for (int nt = 0; nt < 16; nt++)
            #pragma unroll
            for (int e = 0; e < 4; e++) tS[nt][e] = 0.f;

        #pragma unroll
        for (int kk = 0; kk < 4; kk++) {
            const uint32_t boff = ((((uint32_t)lane >> 3) & 1u) << 4) + (uint32_t)kk * 32u;
            const uint32_t brow = (uint32_t)((lane & 7) + ((lane >> 4) << 3));
            #pragma unroll
            for (int g = 0; g < 8; g++) {
                uint32_t bh4[4], bl4[4];
                const uint32_t sw = swz((brow + (uint32_t)g * 16u) * 128u + boff);
                ldsm4(bh4, KhB + sw);
                ldsm4(bl4, KlB + sw);
                #pragma unroll
                for (int q = 0; q < 2; q++) {
                    mma_bf16(tS[g * 2 + q], qah[kk], bh4 + q * 2);
                    mma_bf16(tS[g * 2 + q], qah[kk], bl4 + q * 2);
                    mma_bf16(tS[g * 2 + q], qal[kk], bh4 + q * 2);
                }
            }
        }

        // ---- bias + scale ----
        const int sbase = st * 128, qmin = bm + wm;
        if (sbase + 127 <= qmin - 16) {
            #pragma unroll
            for (int nt = 0; nt < 16; nt++)
                #pragma unroll
                for (int e = 0; e < 4; e++)
                    tS[nt][e] = (tS[nt][e] + ((e < 2) ? blo0 : blo1)) * 0.125f;
        } else if (sbase >= qmin + 31) {
            #pragma unroll
            for (int nt = 0; nt < 16; nt++)
                #pragma unroll
                for (int e = 0; e < 4; e++)
                    tS[nt][e] = (tS[nt][e] + ((e < 2) ? bhi0 : bhi1)) * 0.125f;
        } else {
            #pragma unroll
            for (int nt = 0; nt < 16; nt++)
                #pragma unroll
                for (int e = 0; e < 4; e++) {
                    const int sg = sbase + nt * 8 + (lane & 3) * 2 + (e & 1);
                    const int rl = (e < 2) ? rl0 : rl1;
                    int idx = sg - (bm + rl) + 16;
                    idx = idx < 0 ? 0 : (idx > 32 ? 32 : idx);
                    tS[nt][e] = (tS[nt][e] + prow[rl * NPE + idx]) * 0.125f;
                }
        }

        // ---- online softmax ----
        float mx0 = -1e30f, mx1 = -1e30f;
        #pragma unroll
        for (int nt = 0; nt < 16; nt++) {
            mx0 = fmaxf(mx0, fmaxf(tS[nt][0], tS[nt][1]));
            mx1 = fmaxf(mx1, fmaxf(tS[nt][2], tS[nt][3]));
        }
        mx0 = fmaxf(mx0, __shfl_xor_sync(0xffffffffu, mx0, 1));
        mx0 = fmaxf(mx0, __shfl_xor_sync(0xffffffffu, mx0, 2));
        mx1 = fmaxf(mx1, __shfl_xor_sync(0xffffffffu, mx1, 1));
        mx1 = fmaxf(mx1, __shfl_xor_sync(0xffffffffu, mx1, 2));
        const float M0 = fmaxf(mrun0, mx0), M1 = fmaxf(mrun1, mx1);
        const float a0 = __expf(mrun0 - M0), a1 = __expf(mrun1 - M1);
        mrun0 = M0; mrun1 = M1;
        float s0 = 0.f, s1 = 0.f;
        #pragma unroll
        for (int nt = 0; nt < 16; nt++) {
            tS[nt][0] = __expf(tS[nt][0] - M0); s0 += tS[nt][0];
            tS[nt][1] = __expf(tS[nt][1] - M0); s0 += tS[nt][1];
            tS[nt][2] = __expf(tS[nt][2] - M1); s1 += tS[nt][2];
            tS[nt][3] = __expf(tS[nt][3] - M1); s1 += tS[nt][3];
        }
        s0 += __shfl_xor_sync(0xffffffffu, s0, 1);
        s0 += __shfl_xor_sync(0xffffffffu, s0, 2);
        s1 += __shfl_xor_sync(0xffffffffu, s1, 1);
        s1 += __shfl_xor_sync(0xffffffffu, s1, 2);
        lrun0 = lrun0 * a0 + s0;
        lrun1 = lrun1 * a1 + s1;
        #pragma unroll
        for (int g = 0; g < 8; g++) {
            ctx[g][0] *= a0; ctx[g][1] *= a0;
            ctx[g][2] *= a1; ctx[g][3] *= a1;
        }

        // ---- ctx += P V ----
        #pragma unroll
        for (int c = 0; c < 8; c++) {
            uint32_t ph4[4], pl4[4];
            packhl(tS[2*c][0],   tS[2*c][1],   ph4[0], pl4[0]);
            packhl(tS[2*c][2],   tS[2*c][3],   ph4[1], pl4[1]);
            packhl(tS[2*c+1][0], tS[2*c+1][1], ph4[2], pl4[2]);
            packhl(tS[2*c+1][2], tS[2*c+1][3], ph4[3], pl4[3]);
            const uint32_t vrow  = (uint32_t)(c * 16 + (lane & 7) + ((lane >> 3) & 1) * 8);
            const uint32_t vcolb = (((uint32_t)lane >> 4) << 4);
            #pragma unroll
            for (int g = 0; g < 4; g++) {
                uint32_t vh4[4], vl4[4];
                const uint32_t sw = swz(vrow * 128u + vcolb + (uint32_t)g * 32u);
                ldsm4t(vh4, VhB + sw);
                ldsm4t(vl4, VlB + sw);
                #pragma unroll
                for (int q = 0; q < 2; q++) {
                    mma_bf16(ctx[g * 2 + q], ph4, vh4 + q * 2);
                    mma_bf16(ctx[g * 2 + q], ph4, vl4 + q * 2);
                    mma_bf16(ctx[g * 2 + q], pl4, vh4 + q * 2);
                }
            }
        }
        __syncthreads();
    }

    // ---- epilogue: ctx/l -> hi/lo bf16 [b][q][h*64+d] ----
    const float inv0 = 1.f / lrun0, inv1 = 1.f / lrun1;
    const int b_ = bh >> 4, h_ = bh & 15;
    const int q0 = bm + wm + (lane >> 2);
    #pragma unroll
    for (int g = 0; g < 8; g++) {
        const int col = h_ * 64 + g * 8 + (lane & 3) * 2;
        #pragma unroll
        for (int rr = 0; rr < 2; rr++) {
            const int q = q0 + rr * 8;
            const float inv = rr ? inv1 : inv0;
            const float x0 = ctx[g][rr * 2 + 0] * inv, x1 = ctx[g][rr * 2 + 1] * inv;
            uint32_t ph, pl; packhl(x0, x1, ph, pl);
            const size_t o = ((size_t)b_ * SEQ + q) * DM + col;
            *reinterpret_cast<uint32_t*>(Ch + o) = ph;
            *reinterpret_cast<uint32_t*>(Cl + o) = pl;
        }
    }
}

// ---------------- rel-position projections ----------------
__global__ __launch_bounds__(256)
void relproj2(const bf16* __restrict__ Qh, const bf16* __restrict__ Ql,
              const float* __restrict__ pemb, float* __restrict__ P)
{
    __shared__ float pt[64][34];
    __shared__ float qs[8][64];
    const int tid = threadIdx.x;
    for (int i = tid; i < NPE * 64; i += 256) {
        int j = i >> 6, d = i & 63;
        pt[d][j] = pemb[i];
    }
    __syncthreads();
    const int wid = tid >> 5, l = tid & 31;
    const size_t row = (size_t)blockIdx.x * 8 + wid;
    qs[wid][l]      = __bfloat162float(Qh[row * 64 + l])      + __bfloat162float(Ql[row * 64 + l]);
    qs[wid][l + 32] = __bfloat162float(Qh[row * 64 + 32 + l]) + __bfloat162float(Ql[row * 64 + 32 + l]);
    __syncwarp();
    float acc = 0.f, acc32 = 0.f;
    #pragma unroll
    for (int d = 0; d < 64; d++) {
        float q = qs[wid][d];
        acc   += q * pt[d][l];
        acc32 += q * pt[d][32];
    }
    P[row * NPE + l] = acc;
    if (l == 0) P[row * NPE + 32] = acc32;
}

// ---------------- launch ----------------
extern "C" void kernel_launch(void* const* d_in, const int* in_sizes, int n_in,
                              void* d_out, int out_size)
{
    const float* iQ   = (const float*)d_in[0];
    const float* iK   = (const float*)d_in[1];
    const float* iV   = (const float*)d_in[2];
    const float* Wq   = (const float*)d_in[3];
    const float* Wk   = (const float*)d_in[4];
    const float* Wv   = (const float*)d_in[5];
    const float* Wo   = (const float*)d_in[6];
    const float* pemb = (const float*)d_in[7];
    float* out = (float*)d_out;

    bf16 *Wth, *Wtl, *Ih, *Il, *Qh, *Ql, *Kh, *Kl, *Vh, *Vl, *Ch, *Cl;
    float* P;
    cudaGetSymbolAddress((void**)&Wth, g_Wth);
    cudaGetSymbolAddress((void**)&Wtl, g_Wtl);
    cudaGetSymbolAddress((void**)&Ih,  g_Ih);
    cudaGetSymbolAddress((void**)&Il,  g_Il);
    cudaGetSymbolAddress((void**)&Qh,  g_Qh);
    cudaGetSymbolAddress((void**)&Ql,  g_Ql);
    cudaGetSymbolAddress((void**)&Kh,  g_Kh);
    cudaGetSymbolAddress((void**)&Kl,  g_Kl);
    cudaGetSymbolAddress((void**)&Vh,  g_Vh);
    cudaGetSymbolAddress((void**)&Vl,  g_Vl);
    cudaGetSymbolAddress((void**)&Ch,  g_Ch);
    cudaGetSymbolAddress((void**)&Cl,  g_Cl);
    cudaGetSymbolAddress((void**)&P,   g_P);

    constexpr int SM_GEMM  = 1024 + 2 * 65536;            // 132096
    constexpr int SM_FLASH = 1024 + 32768 + 2 * 65536 + 128 * NPE * 4; // 181760
    cudaFuncSetAttribute(gemm_hl<0>, cudaFuncAttributeMaxDynamicSharedMemorySize, SM_GEMM);
    cudaFuncSetAttribute(gemm_hl<1>, cudaFuncAttributeMaxDynamicSharedMemorySize, SM_GEMM);
    cudaFuncSetAttribute(flash_attn, cudaFuncAttributeMaxDynamicSharedMemorySize, SM_FLASH);

    const int NELEM4 = NB * SEQ * DM / 4;   // float4 count per input

    // 0) prep: transpose+split weights
    transp_w<<<dim3(DM / 32, DM / 32, 4), 256>>>(Wq, Wk, Wv, Wo, Wth, Wtl);

    // 1) projections (input split reused serially)
    dim3 gp(8, 32);
    split_in<<<NELEM4 / 256, 256>>>((const float4*)iQ, Ih, Il);
    gemm_hl<1><<<gp, 256, SM_GEMM>>>(Ih, Il, Wth, Wtl, nullptr, Qh, Ql, DM);
    split_in<<<NELEM4 / 256, 256>>>((const float4*)iK, Ih, Il);
    gemm_hl<1><<<gp, 256, SM_GEMM>>>(Ih, Il, Wth + (size_t)DM * DM, Wtl + (size_t)DM * DM,
                                     nullptr, Kh, Kl, DM);
    split_in<<<NELEM4 / 256, 256>>>((const float4*)iV, Ih, Il);
    gemm_hl<1><<<gp, 256, SM_GEMM>>>(Ih, Il, Wth + (size_t)2 * DM * DM, Wtl + (size_t)2 * DM * DM,
                                     nullptr, Vh, Vl, DM);

    // 2) rel-position projections
    relproj2<<<(BH * SEQ) / 8, 256>>>(Qh, Ql, pemb, P);

    // 3) fused attention -> ctx hi/lo
    flash_attn<<<dim3(SEQ / 128, BH), 256, SM_FLASH>>>(Qh, Ql, Kh, Kl, Vh, Vl, P, Ch, Cl);

    // 4) out = ctx @ Wo
    gemm_hl<0><<<gp, 256, SM_GEMM>>>(Ch, Cl, Wth + (size_t)3 * DM * DM, Wtl + (size_t)3 * DM * DM,
                                     out, nullptr, nullptr, DM);
}

// round 8
// speedup vs baseline: 1.0024x; 1.0024x over previous
#include <cuda_runtime.h>
#include <cuda_bf16.h>
#include <cstdint>

#define SEQ 2048
#define NB 2
#define NH 16
#define AD 64
#define DM 1024
#define BH (NB*NH)
#define NPE 33
typedef __nv_bfloat16 bf16;

// ---------------- scratch (no allocation allowed) ----------------
__device__ bf16 g_Wth[(size_t)4*DM*DM], g_Wtl[(size_t)4*DM*DM];
__device__ bf16 g_Ih[(size_t)NB*SEQ*DM],  g_Il[(size_t)NB*SEQ*DM];
__device__ bf16 g_Qh[(size_t)BH*SEQ*AD],  g_Ql[(size_t)BH*SEQ*AD];
__device__ bf16 g_Kh[(size_t)BH*SEQ*AD],  g_Kl[(size_t)BH*SEQ*AD];
__device__ bf16 g_Vh[(size_t)BH*SEQ*AD],  g_Vl[(size_t)BH*SEQ*AD];
__device__ bf16 g_Ch[(size_t)NB*SEQ*DM],  g_Cl[(size_t)NB*SEQ*DM];
__device__ float g_P[(size_t)BH*SEQ*NPE];

// ---------------- helpers ----------------
__device__ __forceinline__ uint32_t s2u(const void* p) {
    uint32_t a;
    asm("{ .reg .u64 t; cvta.to.shared.u64 t, %1; cvt.u32.u64 %0, t; }" : "=r"(a) : "l"(p));
    return a;
}
__device__ __forceinline__ uint32_t swz(uint32_t o) { return o ^ ((o >> 3) & 0x70); }

__device__ __forceinline__ void ldsm4(uint32_t* r, uint32_t a) {
    asm volatile("ldmatrix.sync.aligned.m8n8.x4.shared.b16 {%0,%1,%2,%3}, [%4];"
                 : "=r"(r[0]), "=r"(r[1]), "=r"(r[2]), "=r"(r[3]) : "r"(a));
}
__device__ __forceinline__ void ldsm4t(uint32_t* r, uint32_t a) {
    asm volatile("ldmatrix.sync.aligned.m8n8.x4.trans.shared.b16 {%0,%1,%2,%3}, [%4];"
                 : "=r"(r[0]), "=r"(r[1]), "=r"(r[2]), "=r"(r[3]) : "r"(a));
}
__device__ __forceinline__ void mma_bf16(float* d, const uint32_t* a, const uint32_t* b) {
    asm volatile("mma.sync.aligned.m16n8k16.row.col.f32.bf16.bf16.f32 "
                 "{%0,%1,%2,%3}, {%4,%5,%6,%7}, {%8,%9}, {%0,%1,%2,%3};"
                 : "+f"(d[0]), "+f"(d[1]), "+f"(d[2]), "+f"(d[3])
                 : "r"(a[0]), "r"(a[1]), "r"(a[2]), "r"(a[3]), "r"(b[0]), "r"(b[1]));
}
#define CP16(dst, src) \
    asm volatile("cp.async.cg.shared.global [%0], [%1], 16;" :: "r"(dst), "l"(src))
#define CPCOMMIT asm volatile("cp.async.commit_group;" ::: "memory")
#define CPWAIT(n) asm volatile("cp.async.wait_group %0;" :: "n"(n) : "memory")

__device__ __forceinline__ void packhl(float x0, float x1, uint32_t& ph, uint32_t& pl) {
    bf16 h0 = __float2bfloat16(x0), h1 = __float2bfloat16(x1);
    ph = ((uint32_t)__bfloat16_as_ushort(h1) << 16) | __bfloat16_as_ushort(h0);
    float l0 = x0 - __bfloat162float(h0), l1 = x1 - __bfloat162float(h1);
    asm("cvt.rn.bf16x2.f32 %0, %1, %2;" : "=r"(pl) : "f"(l1), "f"(l0));
}
__device__ __forceinline__ void cvt_hl(float4 v, uint2& h2, uint2& l2) {
    uint32_t a, b, c, d;
    packhl(v.x, v.y, a, c);
    packhl(v.z, v.w, b, d);
    h2 = make_uint2(a, b); l2 = make_uint2(c, d);
}

// ---------------- prep kernels ----------------
__global__ __launch_bounds__(256)
void split_in(const float4* __restrict__ x, bf16* __restrict__ h, bf16* __restrict__ l)
{
    size_t i = (size_t)blockIdx.x * 256 + threadIdx.x;
    float4 v = x[i];
    uint2 h2, l2; cvt_hl(v, h2, l2);
    *reinterpret_cast<uint2*>(h + i * 4) = h2;
    *reinterpret_cast<uint2*>(l + i * 4) = l2;
}

__global__ __launch_bounds__(256)
void transp_w(const float* __restrict__ W0, const float* __restrict__ W1,
              const float* __restrict__ W2, const float* __restrict__ W3,
              bf16* __restrict__ oh, bf16* __restrict__ ol)
{
    __shared__ float t[32][33];
    const float* W = (blockIdx.z == 0) ? W0 : (blockIdx.z == 1) ? W1
                   : (blockIdx.z == 2) ? W2 : W3;
    bf16* Oh = oh + (size_t)blockIdx.z * DM * DM;
    bf16* Ol = ol + (size_t)blockIdx.z * DM * DM;
    const int tx = threadIdx.x & 31, ty = threadIdx.x >> 5;
    const int x = blockIdx.x * 32 + tx, y = blockIdx.y * 32 + ty;
    #pragma unroll
    for (int j = 0; j < 32; j += 8) t[ty + j][tx] = W[(size_t)(y + j) * DM + x];
    __syncthreads();
    const int xo = blockIdx.y * 32 + tx, yo = blockIdx.x * 32 + ty;
    #pragma unroll
    for (int j = 0; j < 32; j += 8) {
        float v = t[tx][ty + j];
        bf16 h = __float2bfloat16(v);
        Oh[(size_t)(yo + j) * DM + xo] = h;
        Ol[(size_t)(yo + j) * DM + xo] = __float2bfloat16(v - __bfloat162float(h));
    }
}

// ---------------------------------------------------------------------------
// split-bf16 GEMM, pre-split operands.  C[128,128] = A[128,K] * B[128,K]^T.
// EPI 0: fp32 [m][DM].   EPI 1: hi/lo bf16 head-major [bh][s][d].
// ---------------------------------------------------------------------------
template<int EPI>
__global__ __launch_bounds__(256, 1)
void gemm_hl(const bf16* __restrict__ Ah_g, const bf16* __restrict__ Al_g,
             const bf16* __restrict__ Bh_g, const bf16* __restrict__ Bl_g,
             float* __restrict__ Cf, bf16* __restrict__ Oh, bf16* __restrict__ Ol,
             int K)
{
    extern __shared__ char dsm[];
    const uint32_t raw = s2u(dsm);
    const uint32_t sb  = (raw + 1023u) & ~1023u;
    const int tid = threadIdx.x, wid = tid >> 5, lane = tid & 31;
    const int bm = blockIdx.y * 128, bn = blockIdx.x * 128;
    const int wm = (wid >> 1) * 32, wn = (wid & 1) * 64;

    float acc[2][8][4] = {};

    auto load_stage = [&](int buf, int k0) {
        uint32_t base = sb + (uint32_t)buf * 65536u;
        #pragma unroll
        for (int i = 0; i < 16; i++) {
            int c = tid + i * 256;
            int t_ = c >> 10, row = (c >> 3) & 127, j = c & 7;
            const bf16* src =
                (t_ == 0) ? Ah_g + (size_t)(bm + row) * K + k0 + j * 8 :
                (t_ == 1) ? Al_g + (size_t)(bm + row) * K + k0 + j * 8 :
                (t_ == 2) ? Bh_g + (size_t)(bn + row) * K + k0 + j * 8 :
                            Bl_g + (size_t)(bn + row) * K + k0 + j * 8;
            uint32_t dst = base + (uint32_t)t_ * 16384u +
                           swz((uint32_t)row * 128u + (uint32_t)j * 16u);
            CP16(dst, src);
        }
        CPCOMMIT;
    };

    const int NS = K / 64;
    load_stage(0, 0);
    for (int s = 0; s < NS; s++) {
        if (s + 1 < NS) { load_stage((s + 1) & 1, (s + 1) * 64); CPWAIT(1); }
        else           { CPWAIT(0); }
        __syncthreads();
        const uint32_t base = sb + (uint32_t)(s & 1) * 65536u;
        const uint32_t AhB = base, AlB = base + 16384u, BhB = base + 32768u, BlB = base + 49152u;
        #pragma unroll
        for (int kk = 0; kk < 4; kk++) {
            const uint32_t kB = (uint32_t)kk * 32u;
            uint32_t ah[2][4], al_[2][4];
            const uint32_t aoff = (((uint32_t)lane >> 4) << 4) + kB;
            #pragma unroll
            for (int mt = 0; mt < 2; mt++) {
                const uint32_t sw = swz((uint32_t)(wm + mt * 16 + (lane & 15)) * 128u + aoff);
                ldsm4(ah[mt], AhB + sw);
                ldsm4(al_[mt], AlB + sw);
            }
            const uint32_t boff = ((((uint32_t)lane >> 3) & 1u) << 4) + kB;
            const uint32_t brow = (uint32_t)(wn + (lane & 7) + ((lane >> 4) << 3));
            #pragma unroll
            for (int g = 0; g < 4; g++) {
                uint32_t bh4[4], bl4[4];
                const uint32_t sw = swz((brow + (uint32_t)g * 16u) * 128u + boff);
                ldsm4(bh4, BhB + sw);
                ldsm4(bl4, BlB + sw);
                #pragma unroll
                for (int mt = 0; mt < 2; mt++)
                    #pragma unroll
                    for (int q = 0; q < 2; q++) {
                        mma_bf16(acc[mt][g * 2 + q], ah[mt],  bh4 + q * 2);
                        mma_bf16(acc[mt][g * 2 + q], ah[mt],  bl4 + q * 2);
                        mma_bf16(acc[mt][g * 2 + q], al_[mt], bh4 + q * 2);
                    }
            }
        }
        __syncthreads();
    }

    #pragma unroll
    for (int mt = 0; mt < 2; mt++)
        #pragma unroll
        for (int nt = 0; nt < 8; nt++) {
            const int m = bm + wm + mt * 16 + (lane >> 2);
            const int n = bn + wn + nt * 8 + (lane & 3) * 2;
            #pragma unroll
            for (int rr = 0; rr < 2; rr++) {
                const int mm = m + rr * 8;
                const float x0 = acc[mt][nt][rr * 2 + 0], x1 = acc[mt][nt][rr * 2 + 1];
                if constexpr (EPI == 0) {
                    *reinterpret_cast<float2*>(Cf + (size_t)mm * DM + n) = make_float2(x0, x1);
                } else {
                    const int b_ = mm >> 11, s_ = mm & 2047, h_ = n >> 6, d_ = n & 63;
                    const size_t o = (((size_t)(b_ * NH + h_)) * SEQ + s_) * AD + d_;
                    uint32_t ph, pl; packhl(x0, x1, ph, pl);
                    *reinterpret_cast<uint32_t*>(Oh + o) = ph;
                    *reinterpret_cast<uint32_t*>(Ol + o) = pl;
                }
            }
        }
}

// ---------------------------------------------------------------------------
// fused flash attention: (QK^T + bias)/8 -> online softmax -> @V
// grid (SEQ/128, BH), 256 threads, warp owns 16 q-rows.
// ---------------------------------------------------------------------------
__global__ __launch_bounds__(256, 1)
void flash_attn(const bf16* __restrict__ Qh_g, const bf16* __restrict__ Ql_g,
                const bf16* __restrict__ Kh_g, const bf16* __restrict__ Kl_g,
                const bf16* __restrict__ Vh_g, const bf16* __restrict__ Vl_g,
                const float* __restrict__ Pr,
                bf16* __restrict__ Ch, bf16* __restrict__ Cl)
{
    extern __shared__ char dsm[];
    const uint32_t raw = s2u(dsm);
    const uint32_t sb  = (raw + 1023u) & ~1023u;
    char* sp = dsm + (sb - raw);
    const int tid = threadIdx.x, wid = tid >> 5, lane = tid & 31;
    const int bh = blockIdx.y, bm = blockIdx.x * 128;
    const int wm = wid * 16;

    const bf16* Qh = Qh_g + ((size_t)bh * SEQ + bm) * AD;
    const bf16* Ql = Ql_g + ((size_t)bh * SEQ + bm) * AD;
    const bf16* Kh = Kh_g + (size_t)bh * SEQ * AD;
    const bf16* Kl = Kl_g + (size_t)bh * SEQ * AD;
    const bf16* Vh = Vh_g + (size_t)bh * SEQ * AD;
    const bf16* Vl = Vl_g + (size_t)bh * SEQ * AD;

    constexpr uint32_t QOFF = 0, STG = 32768, PROW = 32768 + 2 * 65536;
    float* prow = reinterpret_cast<float*>(sp + PROW);

    auto load_stage = [&](int buf, int s0) {
        uint32_t base = sb + STG + (uint32_t)buf * 65536u;
        #pragma unroll
        for (int i = 0; i < 16; i++) {
            int c = tid + i * 256;
            int t_ = c >> 10, row = (c >> 3) & 127, j = c & 7;
            const bf16* src =
                (t_ == 0) ? Kh + (size_t)(s0 + row) * AD + j * 8 :
                (t_ == 1) ? Kl + (size_t)(s0 + row) * AD + j * 8 :
                (t_ == 2) ? Vh + (size_t)(s0 + row) * AD + j * 8 :
                            Vl + (size_t)(s0 + row) * AD + j * 8;
            uint32_t dst = base + (uint32_t)t_ * 16384u +
                           swz((uint32_t)row * 128u + (uint32_t)j * 16u);
            CP16(dst, src);
        }
        CPCOMMIT;
    };

    // Q tiles (hi/lo) + stage0 in first group
    {
        #pragma unroll
        for (int i = 0; i < 8; i++) {
            int c = tid + i * 256;
            int t_ = c >> 10, row = (c >> 3) & 127, j = c & 7;
            const bf16* src = (t_ ? Ql : Qh) + (size_t)row * AD + j * 8;
            uint32_t dst = sb + QOFF + (uint32_t)t_ * 16384u +
                           swz((uint32_t)row * 128u + (uint32_t)j * 16u);
            CP16(dst, src);
        }
    }
    load_stage(0, 0);   // commits Q + stage0 together

    for (int i = tid; i < 128 * NPE; i += 256)
        prow[i] = Pr[((size_t)bh * SEQ + bm) * NPE + i];

    float ctx[8][4] = {};
    float mrun0 = -1e30f, mrun1 = -1e30f, lrun0 = 0.f, lrun1 = 0.f;
    uint32_t qah[4][4], qal[4][4];
    float blo0 = 0.f, blo1 = 0.f, bhi0 = 0.f, bhi1 = 0.f;
    const int rl0 = wm + (lane >> 2), rl1 = rl0 + 8;

    for (int st = 0; st < 16; st++) {
        if (st + 1 < 16) { load_stage((st + 1) & 1, (st + 1) * 128); CPWAIT(1); }
        else             { CPWAIT(0); }
        __syncthreads();

        if (st == 0) {
            #pragma unroll
            for (int kk = 0; kk < 4; kk++) {
                const uint32_t aoff = (((uint32_t)lane >> 4) << 4) + (uint32_t)kk * 32u;
                const uint32_t sw = swz((uint32_t)(wm + (lane & 15)) * 128u + aoff);
                ldsm4(qah[kk], sb + QOFF + sw);
                ldsm4(qal[kk], sb + QOFF + 16384u + sw);
            }
            blo0 = prow[rl0 * NPE + 0];  bhi0 = prow[rl0 * NPE + 32];
            blo1 = prow[rl1 * NPE + 0];  bhi1 = prow[rl1 * NPE + 32];
        }

        const uint32_t base = sb + STG + (uint32_t)(st & 1) * 65536u;
        const uint32_t KhB = base, KlB = base + 16384u, VhB = base + 32768u, VlB = base + 49152u;

        // ---- S = Q K^T ----
        float tS[16][4];
        #pragma unroll
        for (int nt = 0; nt < 16; nt++)
            #pragma unroll
            for (int e = 0; e < 4; e++) tS[nt][e] = 0.f;

        #pragma unroll
        for (int kk = 0; kk < 4; kk++) {
            const uint32_t boff = ((((uint32_t)lane >> 3) & 1u) << 4) + (uint32_t)kk * 32u;
            const uint32_t brow = (uint32_t)((lane & 7) + ((lane >> 4) << 3));
            #pragma unroll
            for (int g = 0; g < 8; g++) {
                uint32_t bh4[4], bl4[4];
                const uint32_t sw = swz((brow + (uint32_t)g * 16u) * 128u + boff);
                ldsm4(bh4, KhB + sw);
                ldsm4(bl4, KlB + sw);
                #pragma unroll
                for (int q = 0; q < 2; q++) {
                    mma_bf16(tS[g * 2 + q], qah[kk], bh4 + q * 2);
                    mma_bf16(tS[g * 2 + q], qah[kk], bl4 + q * 2);
                    mma_bf16(tS[g * 2 + q], qal[kk], bh4 + q * 2);
                }
            }
        }

        // ---- bias + scale ----
        const int sbase = st * 128, qmin = bm + wm;
        if (sbase + 127 <= qmin - 16) {
            #pragma unroll
            for (int nt = 0; nt < 16; nt++)
                #pragma unroll
                for (int e = 0; e < 4; e++)
                    tS[nt][e] = (tS[nt][e] + ((e < 2) ? blo0 : blo1)) * 0.125f;
        } else if (sbase >= qmin + 31) {
            #pragma unroll
            for (int nt = 0; nt < 16; nt++)
                #pragma unroll
                for (int e = 0; e < 4; e++)
                    tS[nt][e] = (tS[nt][e] + ((e < 2) ? bhi0 : bhi1)) * 0.125f;
        } else {
            #pragma unroll
            for (int nt = 0; nt < 16; nt++)
                #pragma unroll
                for (int e = 0; e < 4; e++) {
                    const int sg = sbase + nt * 8 + (lane & 3) * 2 + (e & 1);
                    const int rl = (e < 2) ? rl0 : rl1;
                    int idx = sg - (bm + rl) + 16;
                    idx = idx < 0 ? 0 : (idx > 32 ? 32 : idx);
                    tS[nt][e] = (tS[nt][e] + prow[rl * NPE + idx]) * 0.125f;
                }
        }

        // ---- online softmax ----
        float mx0 = -1e30f, mx1 = -1e30f;
        #pragma unroll
        for (int nt = 0; nt < 16; nt++) {
            mx0 = fmaxf(mx0, fmaxf(tS[nt][0], tS[nt][1]));
            mx1 = fmaxf(mx1, fmaxf(tS[nt][2], tS[nt][3]));
        }
        mx0 = fmaxf(mx0, __shfl_xor_sync(0xffffffffu, mx0, 1));
        mx0 = fmaxf(mx0, __shfl_xor_sync(0xffffffffu, mx0, 2));
        mx1 = fmaxf(mx1, __shfl_xor_sync(0xffffffffu, mx1, 1));
        mx1 = fmaxf(mx1, __shfl_xor_sync(0xffffffffu, mx1, 2));
        const float M0 = fmaxf(mrun0, mx0), M1 = fmaxf(mrun1, mx1);
        const float a0 = __expf(mrun0 - M0), a1 = __expf(mrun1 - M1);
        mrun0 = M0; mrun1 = M1;
        float s0 = 0.f, s1 = 0.f;
        #pragma unroll
        for (int nt = 0; nt < 16; nt++) {
            tS[nt][0] = __expf(tS[nt][0] - M0); s0 += tS[nt][0];
            tS[nt][1] = __expf(tS[nt][1] - M0); s0 += tS[nt][1];
            tS[nt][2] = __expf(tS[nt][2] - M1); s1 += tS[nt][2];
            tS[nt][3] = __expf(tS[nt][3] - M1); s1 += tS[nt][3];
        }
        s0 += __shfl_xor_sync(0xffffffffu, s0, 1);
        s0 += __shfl_xor_sync(0xffffffffu, s0, 2);
        s1 += __shfl_xor_sync(0xffffffffu, s1, 1);
        s1 += __shfl_xor_sync(0xffffffffu, s1, 2);
        lrun0 = lrun0 * a0 + s0;
        lrun1 = lrun1 * a1 + s1;
        #pragma unroll
        for (int g = 0; g < 8; g++) {
            ctx[g][0] *= a0; ctx[g][1] *= a0;
            ctx[g][2] *= a1; ctx[g][3] *= a1;
        }

        // ---- ctx += P V ----
        #pragma unroll
        for (int c = 0; c < 8; c++) {
            uint32_t ph4[4], pl4[4];
            packhl(tS[2*c][0],   tS[2*c][1],   ph4[0], pl4[0]);
            packhl(tS[2*c][2],   tS[2*c][3],   ph4[1], pl4[1]);
            packhl(tS[2*c+1][0], tS[2*c+1][1], ph4[2], pl4[2]);
            packhl(tS[2*c+1][2], tS[2*c+1][3], ph4[3], pl4[3]);
            const uint32_t vrow  = (uint32_t)(c * 16 + (lane & 7) + ((lane >> 3) & 1) * 8);
            const uint32_t vcolb = (((uint32_t)lane >> 4) << 4);
            #pragma unroll
            for (int g = 0; g < 4; g++) {
                uint32_t vh4[4], vl4[4];
                const uint32_t sw = swz(vrow * 128u + vcolb + (uint32_t)g * 32u);
                ldsm4t(vh4, VhB + sw);
                ldsm4t(vl4, VlB + sw);
                #pragma unroll
                for (int q = 0; q < 2; q++) {
                    mma_bf16(ctx[g * 2 + q], ph4, vh4 + q * 2);
                    mma_bf16(ctx[g * 2 + q], ph4, vl4 + q * 2);
                    mma_bf16(ctx[g * 2 + q], pl4, vh4 + q * 2);
                }
            }
        }
        __syncthreads();
    }

    // ---- epilogue: ctx/l -> hi/lo bf16 [b][q][h*64+d] ----
    const float inv0 = 1.f / lrun0, inv1 = 1.f / lrun1;
    const int b_ = bh >> 4, h_ = bh & 15;
    const int q0 = bm + wm + (lane >> 2);
    #pragma unroll
    for (int g = 0; g < 8; g++) {
        const int col = h_ * 64 + g * 8 + (lane & 3) * 2;
        #pragma unroll
        for (int rr = 0; rr < 2; rr++) {
            const int q = q0 + rr * 8;
            const float inv = rr ? inv1 : inv0;
            const float x0 = ctx[g][rr * 2 + 0] * inv, x1 = ctx[g][rr * 2 + 1] * inv;
            uint32_t ph, pl; packhl(x0, x1, ph, pl);
            const size_t o = ((size_t)b_ * SEQ + q) * DM + col;
            *reinterpret_cast<uint32_t*>(Ch + o) = ph;
            *reinterpret_cast<uint32_t*>(Cl + o) = pl;
        }
    }
}

// ---------------- rel-position projections ----------------
__global__ __launch_bounds__(256)
void relproj2(const bf16* __restrict__ Qh, const bf16* __restrict__ Ql,
              const float* __restrict__ pemb, float* __restrict__ P)
{
    __shared__ float pt[64][34];
    __shared__ float qs[8][64];
    const int tid = threadIdx.x;
    for (int i = tid; i < NPE * 64; i += 256) {
        int j = i >> 6, d = i & 63;
        pt[d][j] = pemb[i];
    }
    __syncthreads();
    const int wid = tid >> 5, l = tid & 31;
    const size_t row = (size_t)blockIdx.x * 8 + wid;
    qs[wid][l]      = __bfloat162float(Qh[row * 64 + l])      + __bfloat162float(Ql[row * 64 + l]);
    qs[wid][l + 32] = __bfloat162float(Qh[row * 64 + 32 + l]) + __bfloat162float(Ql[row * 64 + 32 + l]);
    __syncwarp();
    float acc = 0.f, acc32 = 0.f;
    #pragma unroll
    for (int d = 0; d < 64; d++) {
        float q = qs[wid][d];
        acc   += q * pt[d][l];
        acc32 += q * pt[d][32];
    }
    P[row * NPE + l] = acc;
    if (l == 0) P[row * NPE + 32] = acc32;
}

// ---------------- launch ----------------
extern "C" void kernel_launch(void* const* d_in, const int* in_sizes, int n_in,
                              void* d_out, int out_size)
{
    const float* iQ   = (const float*)d_in[0];
    const float* iK   = (const float*)d_in[1];
    const float* iV   = (const float*)d_in[2];
    const float* Wq   = (const float*)d_in[3];
    const float* Wk   = (const float*)d_in[4];
    const float* Wv   = (const float*)d_in[5];
    const float* Wo   = (const float*)d_in[6];
    const float* pemb = (const float*)d_in[7];
    float* out = (float*)d_out;

    bf16 *Wth, *Wtl, *Ih, *Il, *Qh, *Ql, *Kh, *Kl, *Vh, *Vl, *Ch, *Cl;
    float* P;
    cudaGetSymbolAddress((void**)&Wth, g_Wth);
    cudaGetSymbolAddress((void**)&Wtl, g_Wtl);
    cudaGetSymbolAddress((void**)&Ih,  g_Ih);
    cudaGetSymbolAddress((void**)&Il,  g_Il);
    cudaGetSymbolAddress((void**)&Qh,  g_Qh);
    cudaGetSymbolAddress((void**)&Ql,  g_Ql);
    cudaGetSymbolAddress((void**)&Kh,  g_Kh);
    cudaGetSymbolAddress((void**)&Kl,  g_Kl);
    cudaGetSymbolAddress((void**)&Vh,  g_Vh);
    cudaGetSymbolAddress((void**)&Vl,  g_Vl);
    cudaGetSymbolAddress((void**)&Ch,  g_Ch);
    cudaGetSymbolAddress((void**)&Cl,  g_Cl);
    cudaGetSymbolAddress((void**)&P,   g_P);

    constexpr int SM_GEMM  = 1024 + 2 * 65536;            // 132096
    constexpr int SM_FLASH = 1024 + 32768 + 2 * 65536 + 128 * NPE * 4; // 181760
    cudaFuncSetAttribute(gemm_hl<0>, cudaFuncAttributeMaxDynamicSharedMemorySize, SM_GEMM);
    cudaFuncSetAttribute(gemm_hl<1>, cudaFuncAttributeMaxDynamicSharedMemorySize, SM_GEMM);
    cudaFuncSetAttribute(flash_attn, cudaFuncAttributeMaxDynamicSharedMemorySize, SM_FLASH);

    const int NELEM4 = NB * SEQ * DM / 4;   // float4 count per input

    // 0) prep: transpose+split weights
    transp_w<<<dim3(DM / 32, DM / 32, 4), 256>>>(Wq, Wk, Wv, Wo, Wth, Wtl);

    // 1) projections (input split reused serially)
    dim3 gp(8, 32);
    split_in<<<NELEM4 / 256, 256>>>((const float4*)iQ, Ih, Il);
    gemm_hl<1><<<gp, 256, SM_GEMM>>>(Ih, Il, Wth, Wtl, nullptr, Qh, Ql, DM);
    split_in<<<NELEM4 / 256, 256>>>((const float4*)iK, Ih, Il);
    gemm_hl<1><<<gp, 256, SM_GEMM>>>(Ih, Il, Wth + (size_t)DM * DM, Wtl + (size_t)DM * DM,
                                     nullptr, Kh, Kl, DM);
    split_in<<<NELEM4 / 256, 256>>>((const float4*)iV, Ih, Il);
    gemm_hl<1><<<gp, 256, SM_GEMM>>>(Ih, Il, Wth + (size_t)2 * DM * DM, Wtl + (size_t)2 * DM * DM,
                                     nullptr, Vh, Vl, DM);

    // 2) rel-position projections
    relproj2<<<(BH * SEQ) / 8, 256>>>(Qh, Ql, pemb, P);

    // 3) fused attention -> ctx hi/lo
    flash_attn<<<dim3(SEQ / 128, BH), 256, SM_FLASH>>>(Qh, Ql, Kh, Kl, Vh, Vl, P, Ch, Cl);

    // 4) out = ctx @ Wo
    gemm_hl<0><<<gp, 256, SM_GEMM>>>(Ch, Cl, Wth + (size_t)3 * DM * DM, Wtl + (size_t)3 * DM * DM,
                                     out, nullptr, nullptr, DM);
}